// round 8
// baseline (speedup 1.0000x reference)
#include <cuda_runtime.h>

// ---------------------------------------------------------------------------
// SparseCoupleDeConvTest: stride-2 sparse conv3d (CIN=32 -> COUT=64, K=3)
// followed by its exact adjoint (conv_transpose, transpose_kernel=True),
// masked to the sparse input coordinates, output channel-major.
// ---------------------------------------------------------------------------

typedef unsigned long long ull;

namespace {
constexpr int Dz = 41, Hy = 159, Wx = 159;
constexpr int OD = 20, OH = 79, OW = 79;
constexpr int CIN = 32, COUT = 64;
constexpr int B = 2;
constexpr int NVOX = B * Dz * Hy * Wx;          // 2,073,042
constexpr int NMID = B * OD * OH * OW;          // 249,640
}

// Scratch (allocation-free: __device__ globals)
__device__ int        g_idxmap[NVOX];                   // voxel -> point id or -1
__device__ float      g_mid[(size_t)NMID * COUT];       // dense mid activations (~64 MB)
// w1 repacked: [t][i2][lane] ulonglong2, lane owns out-ch pair (2l,2l+1)
//   .x = (w1[t][2i2  ][2l], w1[t][2i2  ][2l+1])
//   .y = (w1[t][2i2+1][2l], w1[t][2i2+1][2l+1])
__device__ ulonglong2 g_w1q[27 * 16 * 32];
// w2 repacked: [k][jp2][lane(=cin i)] ulonglong2
//   .x = (w2[k][i][4jp2  ], w2[k][i][4jp2+1])
//   .y = (w2[k][i][4jp2+2], w2[k][i][4jp2+3])
__device__ ulonglong2 g_w2q[27 * 16 * 32];

// ---- packed fp32x2 helpers (sm_103a) --------------------------------------
__device__ __forceinline__ ull ffma2(ull a, ull b, ull c) {
    ull d;
    asm("fma.rn.f32x2 %0, %1, %2, %3;" : "=l"(d) : "l"(a), "l"(b), "l"(c));
    return d;
}
__device__ __forceinline__ ull fadd2(ull a, ull b) {
    ull d;
    asm("add.rn.f32x2 %0, %1, %2;" : "=l"(d) : "l"(a), "l"(b));
    return d;
}
__device__ __forceinline__ ull pack2(float x, float y) {
    ull r;
    asm("mov.b64 %0, {%1, %2};" : "=l"(r) : "f"(x), "f"(y));
    return r;
}
__device__ __forceinline__ float2 unpack2(ull a) {
    float2 r;
    asm("mov.b64 {%0, %1}, %2;" : "=f"(r.x), "=f"(r.y) : "l"(a));
    return r;
}

// ---- setup kernels ---------------------------------------------------------

__global__ void zero_out_kernel(float4* __restrict__ out, int n4) {
    int i = blockIdx.x * blockDim.x + threadIdx.x;
    int stride = gridDim.x * blockDim.x;
    float4 z = make_float4(0.f, 0.f, 0.f, 0.f);
    for (; i < n4; i += stride) out[i] = z;
}

__global__ void fill_idx_kernel() {
    int i = blockIdx.x * blockDim.x + threadIdx.x;
    if (i < NVOX) g_idxmap[i] = -1;
}

__global__ void scatter_pts_kernel(const int* __restrict__ coors, int npts) {
    int n = blockIdx.x * blockDim.x + threadIdx.x;
    if (n >= npts) return;
    int4 c = ((const int4*)coors)[n];      // (b, z, y, x)
    g_idxmap[((c.x * Dz + c.y) * Hy + c.z) * Wx + c.w] = n;
}

// w1 layout (K,K,K,CIN,COUT): flat = t*2048 + i*64 + j
__global__ void build_w1q_kernel(const float* __restrict__ w1) {
    int id = blockIdx.x * blockDim.x + threadIdx.x;
    if (id >= 27 * 16 * 32) return;
    int lane = id & 31;
    int i2   = (id >> 5) & 15;
    int t    = id >> 9;
    const float2* s0 = (const float2*)(w1 + t * 2048 + (2 * i2)     * 64 + 2 * lane);
    const float2* s1 = (const float2*)(w1 + t * 2048 + (2 * i2 + 1) * 64 + 2 * lane);
    float2 a = *s0, b = *s1;
    ulonglong2 v;
    v.x = pack2(a.x, a.y);
    v.y = pack2(b.x, b.y);
    g_w1q[id] = v;
}

// w2 layout (K,K,K,CIN,COUT): flat = k*2048 + i*64 + j
__global__ void build_w2q_kernel(const float* __restrict__ w2) {
    int id = blockIdx.x * blockDim.x + threadIdx.x;
    if (id >= 27 * 16 * 32) return;
    int lane = id & 31;          // input channel i
    int jp2  = (id >> 5) & 15;
    int k    = id >> 9;
    float4 f = *(const float4*)(w2 + k * 2048 + lane * 64 + 4 * jp2);
    ulonglong2 v;
    v.x = pack2(f.x, f.y);
    v.y = pack2(f.z, f.w);
    g_w2q[id] = v;
}

// ---- stage 1: sparse gather conv -> dense mid ------------------------------
// One warp per mid voxel. Lane l owns output channels (2l, 2l+1).
// Per occupied tap: each lane loads its own feature once, stages the
// duplicated pair in double-buffered smem, then 16 x (LDS.128 + LDG.128 +
// 2xFFMA2) drives the 32x64 rank-1 update with 4 independent accumulators.
__global__ void __launch_bounds__(256) mid_kernel(const float* __restrict__ features)
{
    __shared__ __align__(16) ull sfeat[8][2][32];
    int gw   = (blockIdx.x * 256 + threadIdx.x) >> 5;
    int w    = threadIdx.x >> 5;
    int lane = threadIdx.x & 31;
    if (gw >= NMID) return;

    int tmp = gw;
    int ox = tmp % OW; tmp /= OW;
    int oy = tmp % OH; tmp /= OH;
    int oz = tmp % OD;
    int b  = tmp / OD;

    int q = -1;
    if (lane < 27) {
        int tz = lane / 9;
        int tr = lane - tz * 9;
        int ty = tr / 3;
        int tx = tr - ty * 3;
        q = g_idxmap[((b * Dz + (2 * oz + tz)) * Hy + (2 * oy + ty)) * Wx + (2 * ox + tx)];
    }
    unsigned occ = __ballot_sync(0xffffffffu, q >= 0);

    ull acc0 = 0ull, acc1 = 0ull, acc2 = 0ull, acc3 = 0ull;
    int buf = 0;

    while (occ) {
        int t = __ffs(occ) - 1;
        occ &= occ - 1;
        int qq = __shfl_sync(0xffffffffu, q, t);
        float f = __ldg(features + (size_t)qq * CIN + lane);   // coalesced 128B
        sfeat[w][buf][lane] = pack2(f, f);
        __syncwarp();
        const ulonglong2* fq = (const ulonglong2*)sfeat[w][buf];
        const ulonglong2* wq = g_w1q + t * 512 + lane;
#pragma unroll
        for (int i2 = 0; i2 < 16; i2 += 2) {
            ulonglong2 fa = fq[i2];
            ulonglong2 fb = fq[i2 + 1];
            ulonglong2 wa = __ldg(wq + (size_t)i2 * 32);
            ulonglong2 wb = __ldg(wq + (size_t)(i2 + 1) * 32);
            acc0 = ffma2(fa.x, wa.x, acc0);
            acc1 = ffma2(fa.y, wa.y, acc1);
            acc2 = ffma2(fb.x, wb.x, acc2);
            acc3 = ffma2(fb.y, wb.y, acc3);
        }
        buf ^= 1;
    }
    // Unconditional store: empty voxels write zeros (no pre-zero of g_mid)
    ((ull*)g_mid)[(size_t)gw * 32 + lane] =
        fadd2(fadd2(acc0, acc1), fadd2(acc2, acc3));
}

// ---- stage 2: adjoint gather at sparse points ------------------------------
// Candidate mid coords per dim: 2o + k = v, k in {0,1,2}, 0 <= o < O.
__device__ __forceinline__ int cands(int v, int O, int* os, int* ks) {
    if (v & 1) { os[0] = v >> 1; ks[0] = 1; return 1; }
    int n = 0, h = v >> 1;
    if (h < O) { os[n] = h;     ks[n] = 0; n++; }
    if (h > 0) { os[n] = h - 1; ks[n] = 2; n++; }
    return n;
}

// One warp per sparse point. Lane l owns input channel i = l.
// Per valid mid offset: warp stages the 64-wide mid row (double-buffered),
// then 16 x (LDS.128 + LDG.128 + 2xFFMA2) against the repacked w2.
__global__ void __launch_bounds__(256) back_kernel(
    const int* __restrict__ coors, int npts, float* __restrict__ out)
{
    __shared__ __align__(16) ull smid[8][2][32];
    int w    = threadIdx.x >> 5;
    int lane = threadIdx.x & 31;
    int n = blockIdx.x * 8 + w;
    if (n >= npts) return;

    int4 c = ((const int4*)coors)[n];
    int b = c.x, z = c.y, y = c.z, x = c.w;

    int oz[2], kz[2], oy[2], ky[2], ox[2], kx[2];
    int na = cands(z, OD, oz, kz);
    int nb = cands(y, OH, oy, ky);
    int nc = cands(x, OW, ox, kx);

    ull acc0 = 0ull, acc1 = 0ull, acc2 = 0ull, acc3 = 0ull;
    const ull* midu = (const ull*)g_mid;
    int buf = 0;

    for (int a = 0; a < na; a++)
        for (int bb = 0; bb < nb; bb++)
            for (int cc = 0; cc < nc; cc++) {
                int mo = ((b * OD + oz[a]) * OH + oy[bb]) * OW + ox[cc];
                int k  = (kz[a] * 3 + ky[bb]) * 3 + kx[cc];
                ull mv = __ldg(midu + (size_t)mo * 32 + lane);   // coalesced 256B
                smid[w][buf][lane] = mv;
                __syncwarp();
                const ulonglong2* mq = (const ulonglong2*)smid[w][buf];
                const ulonglong2* wq = g_w2q + k * 512 + lane;
#pragma unroll
                for (int jp2 = 0; jp2 < 16; jp2 += 2) {
                    ulonglong2 ma = mq[jp2];
                    ulonglong2 mb = mq[jp2 + 1];
                    ulonglong2 wa = __ldg(wq + (size_t)jp2 * 32);
                    ulonglong2 wb = __ldg(wq + (size_t)(jp2 + 1) * 32);
                    acc0 = ffma2(ma.x, wa.x, acc0);
                    acc1 = ffma2(ma.y, wa.y, acc1);
                    acc2 = ffma2(mb.x, wb.x, acc2);
                    acc3 = ffma2(mb.y, wb.y, acc3);
                }
                buf ^= 1;
            }

    float2 r = unpack2(fadd2(fadd2(acc0, acc1), fadd2(acc2, acc3)));
    float v = r.x + r.y;
    // output layout (B, CIN, D, H, W)
    size_t oidx = (((size_t)(b * CIN + lane)) * Dz + z) * ((size_t)Hy * Wx)
                + (size_t)y * Wx + x;
    out[oidx] = v;
}

// ---------------------------------------------------------------------------

extern "C" void kernel_launch(void* const* d_in, const int* in_sizes, int n_in,
                              void* d_out, int out_size) {
    if (n_in < 4) return;
    const float* features = (const float*)d_in[0];
    const int*   coors    = (const int*)d_in[1];
    const float* w1       = (const float*)d_in[n_in - 2];
    const float* w2       = (const float*)d_in[n_in - 1];
    float* out = (float*)d_out;
    int npts = in_sizes[1] / 4;

    // 1) zero output (only sparse points get written later)
    int n4 = out_size / 4;
    zero_out_kernel<<<4096, 256>>>((float4*)out, n4);

    // 2) rebuild voxel -> point index map
    fill_idx_kernel<<<(NVOX + 255) / 256, 256>>>();
    scatter_pts_kernel<<<(npts + 255) / 256, 256>>>(coors, npts);

    // 3) repack weights into 16B-granule, lane-major layouts
    build_w1q_kernel<<<(27 * 16 * 32 + 255) / 256, 256>>>(w1);
    build_w2q_kernel<<<(27 * 16 * 32 + 255) / 256, 256>>>(w2);

    // 4) sparse gather conv -> dense mid
    mid_kernel<<<(NMID + 7) / 8, 256>>>(features);

    // 5) adjoint gather + mask + channel-major scatter
    back_kernel<<<(npts + 7) / 8, 256>>>(coors, npts, out);
}